// round 8
// baseline (speedup 1.0000x reference)
#include <cuda_runtime.h>
#include <cuda_bf16.h>
#include <cstdint>

#define NNODES 100000
#define DIM 128
#define MAXEDGE 1700000
#define CSR_BLOCKS 196
#define CSR_THREADS 512

typedef unsigned int uint;

// ---------------- device scratch (static, no allocation) ----------------
__device__ float g_hA[NNODES * DIM];
__device__ float g_hB[NNODES * DIM];
__device__ float g_agg[NNODES * DIM];
__device__ int   g_cnt[NNODES];
__device__ int   g_tmp[NNODES];
__device__ int   g_rowptr[NNODES + 1];
__device__ int   g_cursor[NNODES];
__device__ int   g_col[MAXEDGE];
__device__ int   g_part[CSR_BLOCKS];
__device__ int   g_partscan[CSR_BLOCKS];
__device__ unsigned g_bar[8];          // grid-barrier slots (monotone, never reset)
__device__ unsigned short g_Wbf[4 * 2 * 2 * 16384];

// ---------------- helpers ----------------
__device__ __forceinline__ uint32_t smem_u32(const void* p) {
    uint32_t a;
    asm("{ .reg .u64 t; cvta.to.shared.u64 t, %1; cvt.u32.u64 %0, t; }" : "=r"(a) : "l"(p));
    return a;
}
__device__ __forceinline__ float4 ldcg4(const float4* p) {
    float4 v;
    asm volatile("ld.global.cg.v4.f32 {%0,%1,%2,%3}, [%4];"
                 : "=f"(v.x), "=f"(v.y), "=f"(v.z), "=f"(v.w) : "l"(p));
    return v;
}
__device__ __forceinline__ void ldsm4(uint32_t addr, uint32_t& r0, uint32_t& r1,
                                      uint32_t& r2, uint32_t& r3) {
    asm volatile("ldmatrix.sync.aligned.m8n8.x4.shared.b16 {%0,%1,%2,%3}, [%4];"
                 : "=r"(r0), "=r"(r1), "=r"(r2), "=r"(r3) : "r"(addr));
}
__device__ __forceinline__ void ldsm4t(uint32_t addr, uint32_t& r0, uint32_t& r1,
                                       uint32_t& r2, uint32_t& r3) {
    asm volatile("ldmatrix.sync.aligned.m8n8.x4.trans.shared.b16 {%0,%1,%2,%3}, [%4];"
                 : "=r"(r0), "=r"(r1), "=r"(r2), "=r"(r3) : "r"(addr));
}
__device__ __forceinline__ void mma_bf16(float* c, uint32_t a0, uint32_t a1,
                                         uint32_t a2, uint32_t a3,
                                         uint32_t b0, uint32_t b1) {
    asm volatile("mma.sync.aligned.m16n8k16.row.col.f32.bf16.bf16.f32 "
                 "{%0,%1,%2,%3}, {%4,%5,%6,%7}, {%8,%9}, {%0,%1,%2,%3};"
                 : "+f"(c[0]), "+f"(c[1]), "+f"(c[2]), "+f"(c[3])
                 : "r"(a0), "r"(a1), "r"(a2), "r"(a3), "r"(b0), "r"(b1));
}
__device__ __forceinline__ void split2(float x, float y, uint& hp, uint& lp) {
    __nv_bfloat16 hx = __float2bfloat16(x), hy = __float2bfloat16(y);
    float rx = x - __bfloat162float(hx);
    float ry = y - __bfloat162float(hy);
    __nv_bfloat16 lx = __float2bfloat16(rx), ly = __float2bfloat16(ry);
    hp = ((uint)__bfloat16_as_ushort(hy) << 16) | (uint)__bfloat16_as_ushort(hx);
    lp = ((uint)__bfloat16_as_ushort(ly) << 16) | (uint)__bfloat16_as_ushort(lx);
}

// grid barrier: ticket-based, monotone counter -> safe across graph replays
__device__ __forceinline__ void gridbar(int slot) {
    __syncthreads();
    if (threadIdx.x == 0) {
        __threadfence();
        unsigned t = atomicAdd(&g_bar[slot], 1u) + 1u;
        unsigned target = ((t - 1u) / CSR_BLOCKS + 1u) * CSR_BLOCKS;
        for (;;) {
            unsigned v;
            asm volatile("ld.acquire.gpu.u32 %0, [%1];" : "=r"(v) : "l"(&g_bar[slot]));
            if (v >= target) break;
            __nanosleep(64);
        }
    }
    __syncthreads();
}

// ---------------- fused CSR build (single kernel, grid-sync) ----------------
__global__ void __launch_bounds__(CSR_THREADS) k_csr(
    const int* __restrict__ src, const int* __restrict__ dst, int E)
{
    __shared__ int s[CSR_THREADS];
    int tid = threadIdx.x;
    int gtid = blockIdx.x * CSR_THREADS + tid;
    int gstride = CSR_BLOCKS * CSR_THREADS;

    for (int i = gtid; i < NNODES; i += gstride) g_cnt[i] = 0;
    gridbar(0);

    for (int e = gtid; e < E; e += gstride) atomicAdd(&g_cnt[dst[e]], 1);
    gridbar(1);

    {
        int i = gtid;
        int v = (i < NNODES) ? g_cnt[i] : 0;
        s[tid] = v;
        __syncthreads();
#pragma unroll
        for (int off = 1; off < CSR_THREADS; off <<= 1) {
            int x = (tid >= off) ? s[tid - off] : 0;
            __syncthreads();
            s[tid] += x;
            __syncthreads();
        }
        if (i < NNODES) g_tmp[i] = s[tid] - v;
        if (tid == CSR_THREADS - 1) g_part[blockIdx.x] = s[tid];
    }
    gridbar(2);

    if (blockIdx.x == 0) {
        int v = (tid < CSR_BLOCKS) ? g_part[tid] : 0;
        s[tid] = v;
        __syncthreads();
#pragma unroll
        for (int off = 1; off < CSR_THREADS; off <<= 1) {
            int x = (tid >= off) ? s[tid - off] : 0;
            __syncthreads();
            s[tid] += x;
            __syncthreads();
        }
        if (tid < CSR_BLOCKS) g_partscan[tid] = s[tid] - v;
    }
    gridbar(3);

    for (int i = gtid; i < NNODES; i += gstride) {
        int r = g_tmp[i] + g_partscan[i >> 9];
        g_rowptr[i] = r;
        g_cursor[i] = r;
    }
    if (gtid == 0) g_rowptr[NNODES] = E;
    gridbar(4);

    for (int e = gtid; e < E; e += gstride) {
        int p = atomicAdd(&g_cursor[dst[e]], 1);
        g_col[p] = src[e];
    }
}

// ---------------- SpMM: agg[i,:] = sum_{j in adj(i)} h[j,:] -------------
__global__ void __launch_bounds__(256) k_spmm(const float* __restrict__ h) {
    int gw = (blockIdx.x * blockDim.x + threadIdx.x) >> 5;
    if (gw >= NNODES) return;
    int lane = threadIdx.x & 31;
    int s = g_rowptr[gw];
    int e = g_rowptr[gw + 1];
    const float4* hv = (const float4*)h;
    float4 accA = make_float4(0.f, 0.f, 0.f, 0.f);
    float4 accB = make_float4(0.f, 0.f, 0.f, 0.f);
    int i = s;
    for (; i + 8 <= e; i += 8) {
        int n0 = g_col[i],     n1 = g_col[i + 1], n2 = g_col[i + 2], n3 = g_col[i + 3];
        int n4 = g_col[i + 4], n5 = g_col[i + 5], n6 = g_col[i + 6], n7 = g_col[i + 7];
        float4 a = ldcg4(&hv[n0 * 32 + lane]);
        float4 b = ldcg4(&hv[n1 * 32 + lane]);
        float4 c = ldcg4(&hv[n2 * 32 + lane]);
        float4 d = ldcg4(&hv[n3 * 32 + lane]);
        float4 p = ldcg4(&hv[n4 * 32 + lane]);
        float4 q = ldcg4(&hv[n5 * 32 + lane]);
        float4 r = ldcg4(&hv[n6 * 32 + lane]);
        float4 t = ldcg4(&hv[n7 * 32 + lane]);
        accA.x += (a.x + b.x) + (c.x + d.x);
        accA.y += (a.y + b.y) + (c.y + d.y);
        accA.z += (a.z + b.z) + (c.z + d.z);
        accA.w += (a.w + b.w) + (c.w + d.w);
        accB.x += (p.x + q.x) + (r.x + t.x);
        accB.y += (p.y + q.y) + (r.y + t.y);
        accB.z += (p.z + q.z) + (r.z + t.z);
        accB.w += (p.w + q.w) + (r.w + t.w);
    }
    for (; i + 4 <= e; i += 4) {
        int n0 = g_col[i], n1 = g_col[i + 1], n2 = g_col[i + 2], n3 = g_col[i + 3];
        float4 a = ldcg4(&hv[n0 * 32 + lane]);
        float4 b = ldcg4(&hv[n1 * 32 + lane]);
        float4 c = ldcg4(&hv[n2 * 32 + lane]);
        float4 d = ldcg4(&hv[n3 * 32 + lane]);
        accA.x += (a.x + b.x) + (c.x + d.x);
        accA.y += (a.y + b.y) + (c.y + d.y);
        accA.z += (a.z + b.z) + (c.z + d.z);
        accA.w += (a.w + b.w) + (c.w + d.w);
    }
    for (; i < e; i++) {
        int n = g_col[i];
        float4 a = ldcg4(&hv[n * 32 + lane]);
        accA.x += a.x; accA.y += a.y; accA.z += a.z; accA.w += a.w;
    }
    accA.x += accB.x; accA.y += accB.y; accA.z += accB.z; accA.w += accB.w;
    ((float4*)g_agg)[gw * 32 + lane] = accA;
}

// ---------------- W pre-split (once per launch) ----------------
__global__ void k_wsplit(const float* __restrict__ Wrel, const float* __restrict__ Wroot) {
    int l = blockIdx.x >> 1, m = blockIdx.x & 1;
    const float* W = (m ? Wroot : Wrel) + l * 16384;
    unsigned short* hip = g_Wbf + ((l * 2 + m) * 2) * 16384;
    unsigned short* lop = hip + 16384;
    for (int idx = threadIdx.x; idx < 16384; idx += blockDim.x) {
        float w = W[idx];
        __nv_bfloat16 h = __float2bfloat16(w);
        float r = w - __bfloat162float(h);
        hip[idx] = __bfloat16_as_ushort(h);
        lop[idx] = __bfloat16_as_ushort(__float2bfloat16(r));
    }
}

// ---------------- tensor-core GEMM (mma.sync bf16, 3-split) + fused epilogue ----
// 512 threads = 16 warps in 4x4 grid; warp tile 32 rows x 32 cols.
#define LDK 136
#define TILE (128 * LDK * 2)          // 34816 B
#define OFF_AHI 0
#define OFF_ALO TILE
#define OFF_W   (2 * TILE)            // [rel hi][rel lo][root hi][root lo]
#define GSM_TOTAL (6 * TILE)          // 208896 B
#define LDC 132
#define OFF_MEAN OFF_W
#define OFF_RS   (OFF_W + 512)

__global__ void __launch_bounds__(512, 1) k_gemm_mma(
    const float* __restrict__ hin, int layer,
    const float* __restrict__ bias,
    const float* __restrict__ gamma, const float* __restrict__ beta,
    float* __restrict__ hout, int mode)
{
    extern __shared__ char smem[];
    uint32_t sb = smem_u32(smem);
    int tid = threadIdx.x;
    int wid = tid >> 5;
    int lane = tid & 31;
    int wr = wid & 3;          // row group: rows wr*32..+31
    int wc = wid >> 2;         // col group: cols wc*32..+31
    int lane15 = lane & 15;
    int laneHi = lane >> 4;
    int rowBase = blockIdx.x * 128;

    // stage 4 pre-split W tiles
    {
        const uint4* wsrc = (const uint4*)(g_Wbf + layer * 4 * 16384);
        for (int tI = 0; tI < 4; tI++) {
            char* dbase = smem + OFF_W + tI * TILE;
            const uint4* sbase = wsrc + tI * 2048;
            for (int i = tid; i < 2048; i += 512) {
                int r = i >> 4, q = i & 15;
                *(uint4*)(dbase + r * (LDK * 2) + q * 16) = __ldg(&sbase[i]);
            }
        }
    }

    float acc[2][4][4];
#pragma unroll
    for (int mt = 0; mt < 2; mt++)
#pragma unroll
        for (int nt = 0; nt < 4; nt++)
#pragma unroll
            for (int q = 0; q < 4; q++) acc[mt][nt][q] = 0.f;

    for (int srci = 0; srci < 2; srci++) {
        const float4* src4 = (const float4*)(srci ? hin : g_agg);
        for (int i = tid; i < 4096; i += 512) {
            int r = i >> 5, c4 = i & 31;
            int grow = rowBase + r;
            float4 v = make_float4(0.f, 0.f, 0.f, 0.f);
            if (grow < NNODES) v = __ldg(&src4[grow * 32 + c4]);
            uint h0, l0, h1, l1;
            split2(v.x, v.y, h0, l0);
            split2(v.z, v.w, h1, l1);
            int idx = r * LDK + c4 * 4;
            *(uint2*)(smem + OFF_AHI + idx * 2) = make_uint2(h0, h1);
            *(uint2*)(smem + OFF_ALO + idx * 2) = make_uint2(l0, l1);
        }
        __syncthreads();

#pragma unroll
        for (int pass = 0; pass < 3; pass++) {
            uint32_t abase = sb + (pass == 2 ? OFF_ALO : OFF_AHI);
            uint32_t wbase = sb + OFF_W + srci * 2 * TILE + (pass == 1 ? TILE : 0);
            uint32_t aAddr0 = abase + ((wr * 32 + lane15) * LDK + laneHi * 8) * 2;
            uint32_t wAddr0 = wbase + (lane15 * LDK + wc * 32 + laneHi * 8) * 2;
#pragma unroll
            for (int ks = 0; ks < 8; ks++) {
                uint32_t A0[4], A1[4];
                uint32_t aAddr = aAddr0 + ks * 32;
                ldsm4(aAddr, A0[0], A0[1], A0[2], A0[3]);
                ldsm4(aAddr + 16 * LDK * 2, A1[0], A1[1], A1[2], A1[3]);
                uint32_t wAddr = wAddr0 + ks * 16 * LDK * 2;
#pragma unroll
                for (int g = 0; g < 2; g++) {
                    uint32_t b0, b1, b2, b3;
                    ldsm4t(wAddr + g * 32, b0, b1, b2, b3);
                    mma_bf16(acc[0][2 * g],     A0[0], A0[1], A0[2], A0[3], b0, b1);
                    mma_bf16(acc[0][2 * g + 1], A0[0], A0[1], A0[2], A0[3], b2, b3);
                    mma_bf16(acc[1][2 * g],     A1[0], A1[1], A1[2], A1[3], b0, b1);
                    mma_bf16(acc[1][2 * g + 1], A1[0], A1[1], A1[2], A1[3], b2, b3);
                }
            }
        }
        __syncthreads();
    }

    // spill accumulators to fp32 smem tile
    float* sC = (float*)smem;
    {
        int r0 = wr * 32 + (lane >> 2);
        int c0 = wc * 32 + (lane & 3) * 2;
#pragma unroll
        for (int mt = 0; mt < 2; mt++)
#pragma unroll
            for (int nt = 0; nt < 4; nt++) {
                int r = r0 + mt * 16;
                int c = c0 + nt * 8;
                sC[r * LDC + c]           = acc[mt][nt][0];
                sC[r * LDC + c + 1]       = acc[mt][nt][1];
                sC[(r + 8) * LDC + c]     = acc[mt][nt][2];
                sC[(r + 8) * LDC + c + 1] = acc[mt][nt][3];
            }
    }
    __syncthreads();

    float* sMean = (float*)(smem + OFF_MEAN);
    float* sRs   = (float*)(smem + OFF_RS);

    // ---- E1: bias/residual/ReLU + row stats (4 threads per row) ----
    if (mode != 2) {
        int r = tid >> 2, h = tid & 3;
        int grow = rowBase + r;
        float s1 = 0.f, s2 = 0.f;
        const float4* b4 = (const float4*)bias;
        const float4* h4 = (const float4*)hin;
#pragma unroll
        for (int j = 0; j < 8; j++) {
            int c4 = h * 8 + j;
            float4 x = *(float4*)&sC[r * LDC + c4 * 4];
            float4 b = __ldg(&b4[c4]);
            x.x += b.x; x.y += b.y; x.z += b.z; x.w += b.w;
            if (mode == 1 && grow < NNODES) {
                float4 hv = __ldg(&h4[grow * 32 + c4]);
                x.x += hv.x; x.y += hv.y; x.z += hv.z; x.w += hv.w;
            }
            x.x = fmaxf(x.x, 0.f); x.y = fmaxf(x.y, 0.f);
            x.z = fmaxf(x.z, 0.f); x.w = fmaxf(x.w, 0.f);
            *(float4*)&sC[r * LDC + c4 * 4] = x;
            s1 += (x.x + x.y) + (x.z + x.w);
            s2 += (x.x * x.x + x.y * x.y) + (x.z * x.z + x.w * x.w);
        }
        s1 += __shfl_xor_sync(0xffffffffu, s1, 1);
        s2 += __shfl_xor_sync(0xffffffffu, s2, 1);
        s1 += __shfl_xor_sync(0xffffffffu, s1, 2);
        s2 += __shfl_xor_sync(0xffffffffu, s2, 2);
        if (h == 0) {
            float mean = s1 * (1.0f / 128.0f);
            float var  = s2 * (1.0f / 128.0f) - mean * mean;
            sMean[r] = mean;
            sRs[r]   = rsqrtf(var + 1e-5f);
        }
    }
    __syncthreads();

    // ---- E2: coalesced LN-apply (or bias-add) + store ----
    {
        float4 gv  = __ldg(&((const float4*)gamma)[lane]);
        float4 btv = __ldg(&((const float4*)beta)[lane]);
        float4 bv  = __ldg(&((const float4*)bias)[lane]);
        float4* o4 = (float4*)hout;
#pragma unroll
        for (int p = 0; p < 8; p++) {
            int r = p * 16 + wid;
            int grow = rowBase + r;
            if (grow >= NNODES) continue;
            float4 x = *(float4*)&sC[r * LDC + lane * 4];
            if (mode != 2) {
                float mean = sMean[r], rs = sRs[r];
                x.x = (x.x - mean) * rs * gv.x + btv.x;
                x.y = (x.y - mean) * rs * gv.y + btv.y;
                x.z = (x.z - mean) * rs * gv.z + btv.z;
                x.w = (x.w - mean) * rs * gv.w + btv.w;
            } else {
                x.x += bv.x; x.y += bv.y; x.z += bv.z; x.w += bv.w;
            }
            o4[grow * 32 + lane] = x;
        }
    }
}

// ---------------- host ----------------
extern "C" void kernel_launch(void* const* d_in, const int* in_sizes, int n_in,
                              void* d_out, int out_size)
{
    const float* in_feat = (const float*)d_in[0];
    const int*   eidx    = (const int*)d_in[1];
    const float* W_rel   = (const float*)d_in[2];
    const float* b_rel   = (const float*)d_in[3];
    const float* W_root  = (const float*)d_in[4];
    const float* gamma   = (const float*)d_in[5];
    const float* beta    = (const float*)d_in[6];
    float* out = (float*)d_out;

    int E = in_sizes[1] / 2;
    const int* src = eidx;
    const int* dst = eidx + E;

    float *hA, *hB;
    cudaGetSymbolAddress((void**)&hA, g_hA);
    cudaGetSymbolAddress((void**)&hB, g_hB);

    cudaFuncSetAttribute(k_gemm_mma, cudaFuncAttributeMaxDynamicSharedMemorySize, GSM_TOTAL);

    int spmm_blocks = (NNODES * 32 + 255) / 256;
    int gemm_blocks = (NNODES + 127) / 128;

    // ncu captures the 4th launch (index 3) -> k_gemm_mma layer 0
    k_csr<<<CSR_BLOCKS, CSR_THREADS>>>(src, dst, E);                                 // 0
    k_spmm<<<spmm_blocks, 256>>>(in_feat);                                           // 1
    k_wsplit<<<8, 256>>>(W_rel, W_root);                                             // 2
    k_gemm_mma<<<gemm_blocks, 512, GSM_TOTAL>>>(in_feat, 0, b_rel, gamma, beta, hA, 0);  // 3 <-- capture
    // layer 1
    k_spmm<<<spmm_blocks, 256>>>(hA);
    k_gemm_mma<<<gemm_blocks, 512, GSM_TOTAL>>>(hA, 1, b_rel + 128, gamma, beta, hB, 1);
    // layer 2
    k_spmm<<<spmm_blocks, 256>>>(hB);
    k_gemm_mma<<<gemm_blocks, 512, GSM_TOTAL>>>(hB, 2, b_rel + 256, gamma, beta, hA, 1);
    // layer 3 (no epilogue)
    k_spmm<<<spmm_blocks, 256>>>(hA);
    k_gemm_mma<<<gemm_blocks, 512, GSM_TOTAL>>>(hA, 3, b_rel + 384, gamma, beta, out, 2);
}

// round 9
// speedup vs baseline: 1.1516x; 1.1516x over previous
#include <cuda_runtime.h>
#include <cuda_bf16.h>
#include <cstdint>

#define NNODES 100000
#define DIM 128
#define MAXEDGE 1700000
#define CSR_BLOCKS 196
#define CSR_THREADS 512

typedef unsigned int uint;

// ---------------- device scratch (static, no allocation) ----------------
__device__ float g_hA[NNODES * DIM];
__device__ float g_hB[NNODES * DIM];
__device__ float g_agg[NNODES * DIM];
__device__ int   g_cnt[NNODES];
__device__ int   g_tmp[NNODES];
__device__ int   g_rowptr[NNODES + 1];
__device__ int   g_cursor[NNODES];
__device__ int   g_col[MAXEDGE];
__device__ int   g_part[CSR_BLOCKS];
__device__ int   g_partscan[CSR_BLOCKS];
__device__ unsigned g_bar[8];          // grid-barrier slots (monotone, never reset)
__device__ unsigned short g_Wbf[4 * 2 * 2 * 16384];

// ---------------- helpers ----------------
__device__ __forceinline__ uint32_t smem_u32(const void* p) {
    uint32_t a;
    asm("{ .reg .u64 t; cvta.to.shared.u64 t, %1; cvt.u32.u64 %0, t; }" : "=r"(a) : "l"(p));
    return a;
}
__device__ __forceinline__ float4 ldcg4(const float4* p) {
    float4 v;
    asm volatile("ld.global.cg.v4.f32 {%0,%1,%2,%3}, [%4];"
                 : "=f"(v.x), "=f"(v.y), "=f"(v.z), "=f"(v.w) : "l"(p));
    return v;
}
__device__ __forceinline__ void ldsm4(uint32_t addr, uint32_t& r0, uint32_t& r1,
                                      uint32_t& r2, uint32_t& r3) {
    asm volatile("ldmatrix.sync.aligned.m8n8.x4.shared.b16 {%0,%1,%2,%3}, [%4];"
                 : "=r"(r0), "=r"(r1), "=r"(r2), "=r"(r3) : "r"(addr));
}
__device__ __forceinline__ void ldsm4t(uint32_t addr, uint32_t& r0, uint32_t& r1,
                                       uint32_t& r2, uint32_t& r3) {
    asm volatile("ldmatrix.sync.aligned.m8n8.x4.trans.shared.b16 {%0,%1,%2,%3}, [%4];"
                 : "=r"(r0), "=r"(r1), "=r"(r2), "=r"(r3) : "r"(addr));
}
__device__ __forceinline__ void mma_bf16(float* c, uint32_t a0, uint32_t a1,
                                         uint32_t a2, uint32_t a3,
                                         uint32_t b0, uint32_t b1) {
    asm volatile("mma.sync.aligned.m16n8k16.row.col.f32.bf16.bf16.f32 "
                 "{%0,%1,%2,%3}, {%4,%5,%6,%7}, {%8,%9}, {%0,%1,%2,%3};"
                 : "+f"(c[0]), "+f"(c[1]), "+f"(c[2]), "+f"(c[3])
                 : "r"(a0), "r"(a1), "r"(a2), "r"(a3), "r"(b0), "r"(b1));
}
__device__ __forceinline__ void split2(float x, float y, uint& hp, uint& lp) {
    __nv_bfloat16 hx = __float2bfloat16(x), hy = __float2bfloat16(y);
    float rx = x - __bfloat162float(hx);
    float ry = y - __bfloat162float(hy);
    __nv_bfloat16 lx = __float2bfloat16(rx), ly = __float2bfloat16(ry);
    hp = ((uint)__bfloat16_as_ushort(hy) << 16) | (uint)__bfloat16_as_ushort(hx);
    lp = ((uint)__bfloat16_as_ushort(ly) << 16) | (uint)__bfloat16_as_ushort(lx);
}

// grid barrier: ticket-based, monotone counter -> safe across graph replays
__device__ __forceinline__ void gridbar(int slot) {
    __syncthreads();
    if (threadIdx.x == 0) {
        __threadfence();
        unsigned t = atomicAdd(&g_bar[slot], 1u) + 1u;
        unsigned target = ((t - 1u) / CSR_BLOCKS + 1u) * CSR_BLOCKS;
        for (;;) {
            unsigned v;
            asm volatile("ld.acquire.gpu.u32 %0, [%1];" : "=r"(v) : "l"(&g_bar[slot]));
            if (v >= target) break;
            __nanosleep(64);
        }
    }
    __syncthreads();
}

// ---------------- fused CSR build (single kernel, grid-sync) ----------------
__global__ void __launch_bounds__(CSR_THREADS) k_csr(
    const int* __restrict__ src, const int* __restrict__ dst, int E)
{
    __shared__ int s[CSR_THREADS];
    int tid = threadIdx.x;
    int gtid = blockIdx.x * CSR_THREADS + tid;
    int gstride = CSR_BLOCKS * CSR_THREADS;

    for (int i = gtid; i < NNODES; i += gstride) g_cnt[i] = 0;
    gridbar(0);

    for (int e = gtid; e < E; e += gstride) atomicAdd(&g_cnt[dst[e]], 1);
    gridbar(1);

    {
        int i = gtid;
        int v = (i < NNODES) ? g_cnt[i] : 0;
        s[tid] = v;
        __syncthreads();
#pragma unroll
        for (int off = 1; off < CSR_THREADS; off <<= 1) {
            int x = (tid >= off) ? s[tid - off] : 0;
            __syncthreads();
            s[tid] += x;
            __syncthreads();
        }
        if (i < NNODES) g_tmp[i] = s[tid] - v;
        if (tid == CSR_THREADS - 1) g_part[blockIdx.x] = s[tid];
    }
    gridbar(2);

    if (blockIdx.x == 0) {
        int v = (tid < CSR_BLOCKS) ? g_part[tid] : 0;
        s[tid] = v;
        __syncthreads();
#pragma unroll
        for (int off = 1; off < CSR_THREADS; off <<= 1) {
            int x = (tid >= off) ? s[tid - off] : 0;
            __syncthreads();
            s[tid] += x;
            __syncthreads();
        }
        if (tid < CSR_BLOCKS) g_partscan[tid] = s[tid] - v;
    }
    gridbar(3);

    for (int i = gtid; i < NNODES; i += gstride) {
        int r = g_tmp[i] + g_partscan[i >> 9];
        g_rowptr[i] = r;
        g_cursor[i] = r;
    }
    if (gtid == 0) g_rowptr[NNODES] = E;
    gridbar(4);

    for (int e = gtid; e < E; e += gstride) {
        int p = atomicAdd(&g_cursor[dst[e]], 1);
        g_col[p] = src[e];
    }
}

// ---------------- SpMM: agg[i,:] = sum_{j in adj(i)} h[j,:] -------------
__global__ void __launch_bounds__(256) k_spmm(const float* __restrict__ h) {
    int gw = (blockIdx.x * blockDim.x + threadIdx.x) >> 5;
    if (gw >= NNODES) return;
    int lane = threadIdx.x & 31;
    int s = g_rowptr[gw];
    int e = g_rowptr[gw + 1];
    const float4* hv = (const float4*)h;
    float4 accA = make_float4(0.f, 0.f, 0.f, 0.f);
    float4 accB = make_float4(0.f, 0.f, 0.f, 0.f);
    int i = s;
    for (; i + 8 <= e; i += 8) {
        int n0 = g_col[i],     n1 = g_col[i + 1], n2 = g_col[i + 2], n3 = g_col[i + 3];
        int n4 = g_col[i + 4], n5 = g_col[i + 5], n6 = g_col[i + 6], n7 = g_col[i + 7];
        float4 a = ldcg4(&hv[n0 * 32 + lane]);
        float4 b = ldcg4(&hv[n1 * 32 + lane]);
        float4 c = ldcg4(&hv[n2 * 32 + lane]);
        float4 d = ldcg4(&hv[n3 * 32 + lane]);
        float4 p = ldcg4(&hv[n4 * 32 + lane]);
        float4 q = ldcg4(&hv[n5 * 32 + lane]);
        float4 r = ldcg4(&hv[n6 * 32 + lane]);
        float4 t = ldcg4(&hv[n7 * 32 + lane]);
        accA.x += (a.x + b.x) + (c.x + d.x);
        accA.y += (a.y + b.y) + (c.y + d.y);
        accA.z += (a.z + b.z) + (c.z + d.z);
        accA.w += (a.w + b.w) + (c.w + d.w);
        accB.x += (p.x + q.x) + (r.x + t.x);
        accB.y += (p.y + q.y) + (r.y + t.y);
        accB.z += (p.z + q.z) + (r.z + t.z);
        accB.w += (p.w + q.w) + (r.w + t.w);
    }
    for (; i + 4 <= e; i += 4) {
        int n0 = g_col[i], n1 = g_col[i + 1], n2 = g_col[i + 2], n3 = g_col[i + 3];
        float4 a = ldcg4(&hv[n0 * 32 + lane]);
        float4 b = ldcg4(&hv[n1 * 32 + lane]);
        float4 c = ldcg4(&hv[n2 * 32 + lane]);
        float4 d = ldcg4(&hv[n3 * 32 + lane]);
        accA.x += (a.x + b.x) + (c.x + d.x);
        accA.y += (a.y + b.y) + (c.y + d.y);
        accA.z += (a.z + b.z) + (c.z + d.z);
        accA.w += (a.w + b.w) + (c.w + d.w);
    }
    for (; i < e; i++) {
        int n = g_col[i];
        float4 a = ldcg4(&hv[n * 32 + lane]);
        accA.x += a.x; accA.y += a.y; accA.z += a.z; accA.w += a.w;
    }
    accA.x += accB.x; accA.y += accB.y; accA.z += accB.z; accA.w += accB.w;
    ((float4*)g_agg)[gw * 32 + lane] = accA;
}

// ---------------- W pre-split (once per launch) ----------------
__global__ void k_wsplit(const float* __restrict__ Wrel, const float* __restrict__ Wroot) {
    int l = blockIdx.x >> 1, m = blockIdx.x & 1;
    const float* W = (m ? Wroot : Wrel) + l * 16384;
    unsigned short* hip = g_Wbf + ((l * 2 + m) * 2) * 16384;
    unsigned short* lop = hip + 16384;
    for (int idx = threadIdx.x; idx < 16384; idx += blockDim.x) {
        float w = W[idx];
        __nv_bfloat16 h = __float2bfloat16(w);
        float r = w - __bfloat162float(h);
        hip[idx] = __bfloat16_as_ushort(h);
        lop[idx] = __bfloat16_as_ushort(__float2bfloat16(r));
    }
}

// ---------------- tensor-core GEMM (mma.sync bf16, 3-split) + fused epilogue ----
// 256 threads, 8 warps in 4x2 grid; warp tile 32 rows x 64 cols (16 MMA / 6 LDSM).
// smem: A-hi, A-lo, W-current = 3 tiles = 104.4 KB -> 2 CTAs/SM.
#define LDK 136
#define TILE (128 * LDK * 2)          // 34816 B
#define OFF_AHI 0
#define OFF_ALO TILE
#define OFF_WC  (2 * TILE)            // current W tile (restaged hi -> lo per source)
#define GSM_TOTAL (3 * TILE)          // 104448 B
#define LDC 132
#define OFF_MEAN OFF_WC               // aliases dead W region after mainloop
#define OFF_RS   (OFF_WC + 512)

__device__ __forceinline__ void gemm_pass(uint32_t abase, uint32_t wbase,
                                          int wr, int wc, int lane15, int laneHi,
                                          float acc[2][8][4])
{
    uint32_t aAddr0 = abase + ((wr * 32 + lane15) * LDK + laneHi * 8) * 2;
    uint32_t wAddr0 = wbase + (lane15 * LDK + wc * 64 + laneHi * 8) * 2;
#pragma unroll
    for (int ks = 0; ks < 8; ks++) {
        uint32_t A0[4], A1[4];
        uint32_t aAddr = aAddr0 + ks * 32;
        ldsm4(aAddr, A0[0], A0[1], A0[2], A0[3]);
        ldsm4(aAddr + 16 * LDK * 2, A1[0], A1[1], A1[2], A1[3]);
        uint32_t wAddr = wAddr0 + ks * 16 * LDK * 2;
#pragma unroll
        for (int g = 0; g < 4; g++) {
            uint32_t b0, b1, b2, b3;
            ldsm4t(wAddr + g * 32, b0, b1, b2, b3);
            mma_bf16(acc[0][2 * g],     A0[0], A0[1], A0[2], A0[3], b0, b1);
            mma_bf16(acc[0][2 * g + 1], A0[0], A0[1], A0[2], A0[3], b2, b3);
            mma_bf16(acc[1][2 * g],     A1[0], A1[1], A1[2], A1[3], b0, b1);
            mma_bf16(acc[1][2 * g + 1], A1[0], A1[1], A1[2], A1[3], b2, b3);
        }
    }
}

__global__ void __launch_bounds__(256, 2) k_gemm_mma(
    const float* __restrict__ hin, int layer,
    const float* __restrict__ bias,
    const float* __restrict__ gamma, const float* __restrict__ beta,
    float* __restrict__ hout, int mode)
{
    extern __shared__ char smem[];
    uint32_t sb = smem_u32(smem);
    int tid = threadIdx.x;
    int wid = tid >> 5;
    int lane = tid & 31;
    int wr = wid & 3;          // rows wr*32..+31
    int wc = wid >> 2;         // cols wc*64..+63
    int lane15 = lane & 15;
    int laneHi = lane >> 4;
    int rowBase = blockIdx.x * 128;

    float acc[2][8][4];
#pragma unroll
    for (int mt = 0; mt < 2; mt++)
#pragma unroll
        for (int nt = 0; nt < 8; nt++)
#pragma unroll
            for (int q = 0; q < 4; q++) acc[mt][nt][q] = 0.f;

    const unsigned short* wlayer = g_Wbf + layer * 4 * 16384;

    for (int srci = 0; srci < 2; srci++) {
        // ---- stage A (fp32 -> bf16 hi/lo) + W-hi ----
        const float4* src4 = (const float4*)(srci ? hin : g_agg);
        for (int i = tid; i < 4096; i += 256) {
            int r = i >> 5, c4 = i & 31;
            int grow = rowBase + r;
            float4 v = make_float4(0.f, 0.f, 0.f, 0.f);
            if (grow < NNODES) v = __ldg(&src4[grow * 32 + c4]);
            uint h0, l0, h1, l1;
            split2(v.x, v.y, h0, l0);
            split2(v.z, v.w, h1, l1);
            int idx = r * LDK + c4 * 4;
            *(uint2*)(smem + OFF_AHI + idx * 2) = make_uint2(h0, h1);
            *(uint2*)(smem + OFF_ALO + idx * 2) = make_uint2(l0, l1);
        }
        {
            const uint4* wsrc = (const uint4*)(wlayer + (srci * 2 + 0) * 16384);
            for (int i = tid; i < 2048; i += 256) {
                int r = i >> 4, q = i & 15;
                *(uint4*)(smem + OFF_WC + r * (LDK * 2) + q * 16) = __ldg(&wsrc[i]);
            }
        }
        __syncthreads();

        // ---- passes using W-hi: Ahi*Whi, Alo*Whi ----
        gemm_pass(sb + OFF_AHI, sb + OFF_WC, wr, wc, lane15, laneHi, acc);
        gemm_pass(sb + OFF_ALO, sb + OFF_WC, wr, wc, lane15, laneHi, acc);
        __syncthreads();

        // ---- restage W-lo ----
        {
            const uint4* wsrc = (const uint4*)(wlayer + (srci * 2 + 1) * 16384);
            for (int i = tid; i < 2048; i += 256) {
                int r = i >> 4, q = i & 15;
                *(uint4*)(smem + OFF_WC + r * (LDK * 2) + q * 16) = __ldg(&wsrc[i]);
            }
        }
        __syncthreads();

        // ---- pass using W-lo: Ahi*Wlo ----
        gemm_pass(sb + OFF_AHI, sb + OFF_WC, wr, wc, lane15, laneHi, acc);
        __syncthreads();
    }

    // ---- spill accumulators to fp32 smem tile (aliases A region) ----
    float* sC = (float*)smem;
    {
        int r0 = wr * 32 + (lane >> 2);
        int c0 = wc * 64 + (lane & 3) * 2;
#pragma unroll
        for (int mt = 0; mt < 2; mt++)
#pragma unroll
            for (int nt = 0; nt < 8; nt++) {
                int r = r0 + mt * 16;
                int c = c0 + nt * 8;
                sC[r * LDC + c]           = acc[mt][nt][0];
                sC[r * LDC + c + 1]       = acc[mt][nt][1];
                sC[(r + 8) * LDC + c]     = acc[mt][nt][2];
                sC[(r + 8) * LDC + c + 1] = acc[mt][nt][3];
            }
    }
    __syncthreads();

    float* sMean = (float*)(smem + OFF_MEAN);
    float* sRs   = (float*)(smem + OFF_RS);

    // ---- E1: bias/residual/ReLU + row stats (2 threads per row) ----
    if (mode != 2) {
        int r = tid >> 1, h = tid & 1;
        int grow = rowBase + r;
        float s1 = 0.f, s2 = 0.f;
        const float4* b4 = (const float4*)bias;
        const float4* h4 = (const float4*)hin;
#pragma unroll
        for (int j = 0; j < 16; j++) {
            int c4 = h * 16 + j;
            float4 x = *(float4*)&sC[r * LDC + c4 * 4];
            float4 b = __ldg(&b4[c4]);
            x.x += b.x; x.y += b.y; x.z += b.z; x.w += b.w;
            if (mode == 1 && grow < NNODES) {
                float4 hv = __ldg(&h4[grow * 32 + c4]);
                x.x += hv.x; x.y += hv.y; x.z += hv.z; x.w += hv.w;
            }
            x.x = fmaxf(x.x, 0.f); x.y = fmaxf(x.y, 0.f);
            x.z = fmaxf(x.z, 0.f); x.w = fmaxf(x.w, 0.f);
            *(float4*)&sC[r * LDC + c4 * 4] = x;
            s1 += (x.x + x.y) + (x.z + x.w);
            s2 += (x.x * x.x + x.y * x.y) + (x.z * x.z + x.w * x.w);
        }
        s1 += __shfl_xor_sync(0xffffffffu, s1, 1);
        s2 += __shfl_xor_sync(0xffffffffu, s2, 1);
        if (h == 0) {
            float mean = s1 * (1.0f / 128.0f);
            float var  = s2 * (1.0f / 128.0f) - mean * mean;
            sMean[r] = mean;
            sRs[r]   = rsqrtf(var + 1e-5f);
        }
    }
    __syncthreads();

    // ---- E2: coalesced LN-apply (or bias-add) + store ----
    {
        float4 gv  = __ldg(&((const float4*)gamma)[lane]);
        float4 btv = __ldg(&((const float4*)beta)[lane]);
        float4 bv  = __ldg(&((const float4*)bias)[lane]);
        float4* o4 = (float4*)hout;
#pragma unroll
        for (int p = 0; p < 16; p++) {
            int r = p * 8 + wid;
            int grow = rowBase + r;
            if (grow >= NNODES) continue;
            float4 x = *(float4*)&sC[r * LDC + lane * 4];
            if (mode != 2) {
                float mean = sMean[r], rs = sRs[r];
                x.x = (x.x - mean) * rs * gv.x + btv.x;
                x.y = (x.y - mean) * rs * gv.y + btv.y;
                x.z = (x.z - mean) * rs * gv.z + btv.z;
                x.w = (x.w - mean) * rs * gv.w + btv.w;
            } else {
                x.x += bv.x; x.y += bv.y; x.z += bv.z; x.w += bv.w;
            }
            o4[grow * 32 + lane] = x;
        }
    }
}

// ---------------- host ----------------
extern "C" void kernel_launch(void* const* d_in, const int* in_sizes, int n_in,
                              void* d_out, int out_size)
{
    const float* in_feat = (const float*)d_in[0];
    const int*   eidx    = (const int*)d_in[1];
    const float* W_rel   = (const float*)d_in[2];
    const float* b_rel   = (const float*)d_in[3];
    const float* W_root  = (const float*)d_in[4];
    const float* gamma   = (const float*)d_in[5];
    const float* beta    = (const float*)d_in[6];
    float* out = (float*)d_out;

    int E = in_sizes[1] / 2;
    const int* src = eidx;
    const int* dst = eidx + E;

    float *hA, *hB;
    cudaGetSymbolAddress((void**)&hA, g_hA);
    cudaGetSymbolAddress((void**)&hB, g_hB);

    cudaFuncSetAttribute(k_gemm_mma, cudaFuncAttributeMaxDynamicSharedMemorySize, GSM_TOTAL);

    int spmm_blocks = (NNODES * 32 + 255) / 256;
    int gemm_blocks = (NNODES + 127) / 128;

    // ncu captures the 4th launch (index 3) -> k_gemm_mma layer 0
    k_csr<<<CSR_BLOCKS, CSR_THREADS>>>(src, dst, E);                                 // 0
    k_spmm<<<spmm_blocks, 256>>>(in_feat);                                           // 1
    k_wsplit<<<8, 256>>>(W_rel, W_root);                                             // 2
    k_gemm_mma<<<gemm_blocks, 256, GSM_TOTAL>>>(in_feat, 0, b_rel, gamma, beta, hA, 0);  // 3 <-- capture
    // layer 1
    k_spmm<<<spmm_blocks, 256>>>(hA);
    k_gemm_mma<<<gemm_blocks, 256, GSM_TOTAL>>>(hA, 1, b_rel + 128, gamma, beta, hB, 1);
    // layer 2
    k_spmm<<<spmm_blocks, 256>>>(hB);
    k_gemm_mma<<<gemm_blocks, 256, GSM_TOTAL>>>(hB, 2, b_rel + 256, gamma, beta, hA, 1);
    // layer 3 (no epilogue)
    k_spmm<<<spmm_blocks, 256>>>(hA);
    k_gemm_mma<<<gemm_blocks, 256, GSM_TOTAL>>>(hA, 3, b_rel + 384, gamma, beta, out, 2);
}